// round 14
// baseline (speedup 1.0000x reference)
#include <cuda_runtime.h>

#define B_ROWS   8192
#define NBINS    125
#define M_CAND   4096
#define NTOT     (NBINS * M_CAND)
#define NTHREADS 128
#define NWARPS   4
#define EARTH_R  3958.8f
#define DEG2RAD  0.017453292519943295f
#define LOG2E    1.4426950408889634f
#define K0_CONST (-4.0f * EARTH_R * LOG2E)   /* chord-space logit slope, log2 */

// Static scratch (no allocations allowed)
__device__ float4 g_xyz[NTOT];     // candidate unit vectors (x,y,z,0)
__device__ float4 g_rowv[B_ROWS];  // row unit vectors
__device__ int2   g_meta[B_ROWS];  // (base index, count) per row
__device__ float2 g_sv[B_ROWS];    // (soft, valid) per row

// ---------------------------------------------------------------------------
// Kernel 1 (merged prep): candidates -> unit vectors (2 per thread, float4
// load); rows -> unit vector + (base, count) meta.
// ---------------------------------------------------------------------------
__global__ __launch_bounds__(256)
void prep_kernel(const float4* __restrict__ bin_coords4,
                 const float* __restrict__ preds,
                 const long long* __restrict__ x_vals,
                 const long long* __restrict__ bin_counts) {
    int i = blockIdx.x * 256 + threadIdx.x;
    if (i < NTOT / 2) {
        float4 cc = __ldg(&bin_coords4[i]);   // two (lon, lat) pairs
        float slat0, clat0, slon0, clon0;
        float slat1, clat1, slon1, clon1;
        __sincosf(cc.y * DEG2RAD, &slat0, &clat0);
        __sincosf(cc.x * DEG2RAD, &slon0, &clon0);
        __sincosf(cc.w * DEG2RAD, &slat1, &clat1);
        __sincosf(cc.z * DEG2RAD, &slon1, &clon1);
        g_xyz[2 * i]     = make_float4(clat0 * clon0, clat0 * slon0, slat0, 0.0f);
        g_xyz[2 * i + 1] = make_float4(clat1 * clon1, clat1 * slon1, slat1, 0.0f);
    } else if (i < NTOT / 2 + B_ROWS) {
        int b = i - NTOT / 2;
        long long bin_id = x_vals[b * 3 + 0] * 25 + x_vals[b * 3 + 1] * 5 + x_vals[b * 3 + 2];
        if (bin_id < 0) bin_id = 0;
        if (bin_id >= NBINS) bin_id = NBINS - 1;
        int count = (int)bin_counts[bin_id];
        if (count < 0) count = 0;
        if (count > M_CAND) count = M_CAND;
        float lon = preds[b * 2 + 0] * DEG2RAD;
        float lat = preds[b * 2 + 1] * DEG2RAD;
        float slat, clat, slon, clon;
        sincosf(lat, &slat, &clat);           // libm accuracy once per row
        sincosf(lon, &slon, &clon);
        g_rowv[b] = make_float4(clat * clon, clat * slon, slat, 0.0f);
        g_meta[b] = make_int2((int)bin_id * M_CAND, count);
    }
}

// ---------------------------------------------------------------------------
// Kernel 2: row-centric single pass, online chord-space logsumexp with FOUR
// independent accumulators per thread (shortens the loop-carried chain).
// ---------------------------------------------------------------------------
__global__ __launch_bounds__(NTHREADS)
void softbin_main_kernel() {
    __shared__ float sh_m[NWARPS];
    __shared__ float sh_s[NWARPS];

    const int b    = blockIdx.x;
    const int tid  = threadIdx.x;
    const int warp = tid >> 5;
    const int lane = tid & 31;

    const int2  mt  = g_meta[b];
    const int base  = mt.x;
    const int count = mt.y;
    const float4 rv = g_rowv[b];              // broadcast LDG.128
    const float px = rv.x, py = rv.y, pz = rv.z;

    const float4* __restrict__ cand = g_xyz + base;

    // Four independent online states
    float m0 = 1.0e30f, s0 = 0.0f;
    float m1 = 1.0e30f, s1 = 0.0f;
    float m2 = 1.0e30f, s2a = 0.0f;
    float m3 = 1.0e30f, s3 = 0.0f;

    int j = tid;
    for (; j + 3 * NTHREADS < count; j += 4 * NTHREADS) {
        float4 c0 = __ldg(&cand[j]);
        float4 c1 = __ldg(&cand[j + NTHREADS]);
        float4 c2 = __ldg(&cand[j + 2 * NTHREADS]);
        float4 c3 = __ldg(&cand[j + 3 * NTHREADS]);
        {
            float dx = px - c0.x, dy = py - c0.y, dz = pz - c0.z;
            float cc = __fsqrt_rn(fmaf(dx, dx, fmaf(dy, dy, dz * dz)));
            float e  = exp2f(K0_CONST * fabsf(cc - m0));
            s0 = (cc < m0) ? fmaf(s0, e, 1.0f) : (s0 + e);
            m0 = fminf(m0, cc);
        }
        {
            float dx = px - c1.x, dy = py - c1.y, dz = pz - c1.z;
            float cc = __fsqrt_rn(fmaf(dx, dx, fmaf(dy, dy, dz * dz)));
            float e  = exp2f(K0_CONST * fabsf(cc - m1));
            s1 = (cc < m1) ? fmaf(s1, e, 1.0f) : (s1 + e);
            m1 = fminf(m1, cc);
        }
        {
            float dx = px - c2.x, dy = py - c2.y, dz = pz - c2.z;
            float cc = __fsqrt_rn(fmaf(dx, dx, fmaf(dy, dy, dz * dz)));
            float e  = exp2f(K0_CONST * fabsf(cc - m2));
            s2a = (cc < m2) ? fmaf(s2a, e, 1.0f) : (s2a + e);
            m2 = fminf(m2, cc);
        }
        {
            float dx = px - c3.x, dy = py - c3.y, dz = pz - c3.z;
            float cc = __fsqrt_rn(fmaf(dx, dx, fmaf(dy, dy, dz * dz)));
            float e  = exp2f(K0_CONST * fabsf(cc - m3));
            s3 = (cc < m3) ? fmaf(s3, e, 1.0f) : (s3 + e);
            m3 = fminf(m3, cc);
        }
    }
    for (; j < count; j += NTHREADS) {
        float4 c0 = __ldg(&cand[j]);
        float dx = px - c0.x, dy = py - c0.y, dz = pz - c0.z;
        float cc = __fsqrt_rn(fmaf(dx, dx, fmaf(dy, dy, dz * dz)));
        float e  = exp2f(K0_CONST * fabsf(cc - m0));
        s0 = (cc < m0) ? fmaf(s0, e, 1.0f) : (s0 + e);
        m0 = fminf(m0, cc);
    }

    // Merge accumulators pairwise (exact logsumexp algebra)
    {
        float mn = fminf(m0, m1);
        s0 = s0 * exp2f(K0_CONST * (m0 - mn)) + s1 * exp2f(K0_CONST * (m1 - mn));
        m0 = mn;
    }
    {
        float mn = fminf(m2, m3);
        s2a = s2a * exp2f(K0_CONST * (m2 - mn)) + s3 * exp2f(K0_CONST * (m3 - mn));
        m2 = mn;
    }
    {
        float mn = fminf(m0, m2);
        s0 = s0 * exp2f(K0_CONST * (m0 - mn)) + s2a * exp2f(K0_CONST * (m2 - mn));
        m0 = mn;
    }

    // Warp-level (m, s) combine
    #pragma unroll
    for (int off = 16; off > 0; off >>= 1) {
        float mo = __shfl_xor_sync(0xffffffffu, m0, off);
        float so = __shfl_xor_sync(0xffffffffu, s0, off);
        float mn = fminf(m0, mo);
        s0 = s0 * exp2f(K0_CONST * (m0 - mn))
           + so * exp2f(K0_CONST * (mo - mn));
        m0 = mn;
    }
    if (lane == 0) { sh_m[warp] = m0; sh_s[warp] = s0; }
    __syncthreads();

    if (tid == 0) {
        float M0 = sh_m[0], S0 = sh_s[0];
        #pragma unroll
        for (int w = 1; w < NWARPS; ++w) {
            float mo = sh_m[w], so = sh_s[w];
            float mn = fminf(M0, mo);
            S0 = S0 * exp2f(K0_CONST * (M0 - mn))
               + so * exp2f(K0_CONST * (mo - mn));
            M0 = mn;
        }
        float soft = 0.0f;
        if (count > 0) {
            float d_min = (2.0f * EARTH_R) * asinf(fminf(0.5f * M0, 1.0f));
            soft = d_min - 0.25f * logf(S0);
        }
        g_sv[b] = make_float2(soft, (count > 0) ? 1.0f : 0.0f);
    }
}

// ---------------------------------------------------------------------------
// Kernel 3: deterministic single-block reduction (separate launch = full
// visibility; fixed summation order). Reads g_sv as float4 (2 rows/load).
// ---------------------------------------------------------------------------
__global__ __launch_bounds__(1024)
void softbin_reduce_kernel(float* __restrict__ out) {
    __shared__ float rs[1024];
    __shared__ float rv[1024];
    const int tid = threadIdx.x;
    const float4* __restrict__ sv4 = (const float4*)g_sv;  // 16B-aligned global
    float ss = 0.0f, vv = 0.0f;
    #pragma unroll
    for (int i = tid; i < B_ROWS / 2; i += 1024) {
        float4 v = __ldg(&sv4[i]);      // (soft0, valid0, soft1, valid1)
        ss += v.x + v.z;
        vv += v.y + v.w;
    }
    rs[tid] = ss;
    rv[tid] = vv;
    __syncthreads();
    #pragma unroll
    for (int off = 512; off > 0; off >>= 1) {
        if (tid < off) {
            rs[tid] += rs[tid + off];
            rv[tid] += rv[tid + off];
        }
        __syncthreads();
    }
    if (tid == 0) out[0] = rs[0] / fmaxf(rv[0], 1.0f);
}

extern "C" void kernel_launch(void* const* d_in, const int* in_sizes, int n_in,
                              void* d_out, int out_size) {
    // Identify inputs by element count (all four are distinct).
    const float*     preds      = 0;   // 16384
    const float*     bin_coords = 0;   // 1024000
    const long long* x_vals     = 0;   // 24576
    const long long* bin_counts = 0;   // 125
    for (int i = 0; i < n_in; ++i) {
        switch (in_sizes[i]) {
            case 16384:   preds      = (const float*)d_in[i];     break;
            case 1024000: bin_coords = (const float*)d_in[i];     break;
            case 24576:   x_vals     = (const long long*)d_in[i]; break;
            case 125:     bin_counts = (const long long*)d_in[i]; break;
        }
    }
    float* out = (float*)d_out;

    const int prep_threads = NTOT / 2 + B_ROWS;
    prep_kernel<<<(prep_threads + 255) / 256, 256>>>(
        (const float4*)bin_coords, preds, x_vals, bin_counts);
    softbin_main_kernel<<<B_ROWS, NTHREADS>>>();
    softbin_reduce_kernel<<<1, 1024>>>(out);
}